// round 8
// baseline (speedup 1.0000x reference)
#include <cuda_runtime.h>
#include <math.h>

#define NN 10000
#define NE 160000
#define FD 128
#define NBASIS 8
#define NHID 64
#define NSPEC 10
#define PERM_SZ (NN + 16*NSPEC)
#define RMAXF 5.0f
#define PI_F 3.14159265358979323846f

// ---------------- device scratch (static, no allocations) ----------------
__device__ __align__(16) float g_rb[NE*NBASIS];     // radial basis per edge [E][8]
__device__ __align__(16) float g_scal[NN*FD];       // node scalar features
__device__ __align__(16) float g_agg[NN*FD];        // aggregated messages
__device__ __align__(16) float g_w2t[2*NHID*FD];    // W2 l=0 cols, transposed [layer][j][ch]
__device__ int   g_cnt[NSPEC];
__device__ int   g_cur[NSPEC];
__device__ int   g_off[NSPEC+1];
__device__ int   g_perm[PERM_SZ];

// ---------------- helpers ----------------------------------------------------
__device__ __forceinline__ unsigned tf32r(float x){
    unsigned u; asm("cvt.rna.tf32.f32 %0, %1;" : "=r"(u) : "f"(x)); return u;
}
__device__ __forceinline__ void mma8(float* c, uint4 a, unsigned b0, unsigned b1){
    asm("mma.sync.aligned.m16n8k8.row.col.f32.tf32.tf32.f32 "
        "{%0,%1,%2,%3},{%4,%5,%6,%7},{%8,%9},{%0,%1,%2,%3};"
        : "+f"(c[0]), "+f"(c[1]), "+f"(c[2]), "+f"(c[3])
        : "r"(a.x), "r"(a.y), "r"(a.z), "r"(a.w), "r"(b0), "r"(b1));
}
__device__ __forceinline__ void red2(float* p, float a, float b){
    asm volatile("red.global.add.v2.f32 [%0], {%1,%2};"
                 :: "l"(p), "f"(a), "f"(b) : "memory");
}

// ---------------- geometry: radial basis (sh[0]==1 is all we need) ----------
__global__ void k_geom(const float* __restrict__ vec){
    int e = blockIdx.x*256 + threadIdx.x;
    if (e >= NE) return;
    float x = vec[3*e+0], y = vec[3*e+1], z = vec[3*e+2];
    float r = sqrtf(x*x + y*y + z*z);
    r = fmaxf(r, 1e-9f);
    float rc  = fminf(r, RMAXF);
    float cut = 0.5f*(__cosf(PI_F*rc/RMAXF) + 1.0f);
    float pref = sqrtf(2.0f/RMAXF) / r * cut;
    float arg = PI_F * r / RMAXF;
    float s1 = __sinf(arg), c2 = 2.0f*__cosf(arg);
    float sm1 = 0.0f, s = s1;
    #pragma unroll
    for (int n = 1; n <= NBASIS; n++){
        g_rb[e*NBASIS + n - 1] = pref * s;
        float sn = c2*s - sm1;
        sm1 = s; s = sn;
    }
}

// ---------------- init: scal = emb_W[specie]; agg = 0; species counts -------
__global__ void k_init(const int* __restrict__ spec, const float* __restrict__ emb){
    int idx = blockIdx.x*256 + threadIdx.x;
    if (idx >= NN*FD) return;
    int n = idx >> 7, f = idx & 127;
    int s = spec[n];
    g_scal[idx] = emb[s*FD + f];
    g_agg[idx]  = 0.0f;
    if (f == 0) atomicAdd(&g_cnt[s], 1);
}

__global__ void k_cnt0(){ if (threadIdx.x < NSPEC){ g_cnt[threadIdx.x] = 0; g_cur[threadIdx.x] = 0; } }

// ---------------- W2 transpose + perm init -----------------------------------
__global__ void k_w2t(const float* __restrict__ W2){
    int idx = blockIdx.x*256 + threadIdx.x;
    if (idx < 2*NHID*FD){
        int l = idx >> 13, rem = idx & 8191;
        int j = rem >> 7, ch = rem & 127;
        g_w2t[idx] = W2[l*NHID*FD*4 + j*FD*4 + ch*4];
    }
    if (idx < PERM_SZ) g_perm[idx] = -1;
}

__global__ void k_b2(){
    if (threadIdx.x == 0){
        int o = 0;
        for (int s = 0; s < NSPEC; s++){ g_off[s] = o; o += (g_cnt[s] + 15) & ~15; }
        g_off[NSPEC] = o;
    }
}
__global__ void k_b4(const int* __restrict__ spec){
    int n = blockIdx.x*256 + threadIdx.x;
    if (n < NN){
        int s = spec[n];
        int p = atomicAdd(&g_cur[s], 1);
        g_perm[g_off[s] + p] = n;
    }
}

// ---------------- fused edge kernel: in-smem tf32 MMA -------------------------
// 256 threads = 8 warps; warp w owns 16-ch slice. 4 chunks of 32 edges/block.
// Per chunk: h=silu(rb@W1+b1) -> smem; hi/lo tf32 frag-ize -> smem; 3-pass
// mma (Ahi*Bhi + Alo*Bhi + Ahi*Blo, fp32-class accuracy, validated in R6);
// scatter straight from C frags via red.v2.
__global__ __launch_bounds__(256) void k_edge(
    const float* __restrict__ W1, const float* __restrict__ b1,
    const float* __restrict__ W2t,
    const int* __restrict__ snd, const int* __restrict__ rcv)
{
    __shared__ float h_s[NHID*34];            // [j][e], pitch 34
    __shared__ float frag[32*128];            // 16 KB A-fragment buffer
    __shared__ float W1s[NBASIS*NHID];
    __shared__ float b1s[NHID];
    __shared__ float rb_s[32*9];
    __shared__ int   snd_s[32], rcv_s[32];
    int tid = threadIdx.x, lane = tid & 31, w = tid >> 5;

    for (int i = tid; i < NBASIS*NHID; i += 256) W1s[i] = W1[i];
    if (tid < NHID) b1s[tid] = b1[tid];

    // ---- B fragments (hi/lo) resident in registers for the whole block ----
    unsigned Bh[8][2][2], Bl[8][2][2];
    {
        int bk = lane & 3, bn = lane >> 2;
        #pragma unroll
        for (int kt = 0; kt < 8; kt++)
            #pragma unroll
            for (int nt = 0; nt < 2; nt++)
                #pragma unroll
                for (int hh = 0; hh < 2; hh++){
                    int j  = kt*8 + bk + hh*4;
                    int ch = w*16 + nt*8 + bn;
                    float wv = W2t[j*FD + ch];
                    unsigned whi = tf32r(wv);
                    Bh[kt][nt][hh] = whi;
                    Bl[kt][nt][hh] = tf32r(wv - __uint_as_float(whi));
                }
    }

    int er = lane >> 2, ec2 = 2*(lane & 3);

    for (int c = 0; c < 4; c++){
        int e0 = (blockIdx.x*4 + c)*32;
        __syncthreads();                      // prev chunk GEMM reads done
        if (tid < 32) snd_s[tid] = snd[e0 + tid];
        else if (tid < 64) rcv_s[tid-32] = rcv[e0 + tid - 32];
        if (tid < 128){
            int i0 = tid*2;
            rb_s[(i0>>3)*9 + (i0&7)]       = g_rb[e0*NBASIS + i0];
            rb_s[((i0+1)>>3)*9 + ((i0+1)&7)] = g_rb[e0*NBASIS + i0 + 1];
        }
        __syncthreads();

        // ---- A1: h = silu(rb @ W1 + b1); warp w -> j in [8w, 8w+8), lane=edge
        {
            float rbv[NBASIS];
            #pragma unroll
            for (int k = 0; k < NBASIS; k++) rbv[k] = rb_s[lane*9 + k];
            #pragma unroll
            for (int q = 0; q < 8; q++){
                int j = w*8 + q;
                float a = b1s[j];
                #pragma unroll
                for (int k = 0; k < NBASIS; k++)
                    a = fmaf(rbv[k], W1s[k*NHID + j], a);
                h_s[j*34 + lane] = __fdividef(a, 1.0f + __expf(-a));
            }
        }
        __syncthreads();

        // ---- A2: fragment-ize (R6-validated layout); warp w -> q in [4w,4w+4)
        #pragma unroll
        for (int qq = 0; qq < 4; qq++){
            int q = w*4 + qq;
            int p = q >> 4, kt = (q >> 1) & 7, mt = q & 1;
            unsigned hv[4];
            #pragma unroll
            for (int a = 0; a < 4; a++){
                int rr = (lane >> 2) | ((a & 1) << 3);
                int cc = (lane & 3) | ((a >> 1) << 2);
                float v = h_s[(kt*8 + cc)*34 + mt*16 + rr];
                unsigned hi = tf32r(v);
                hv[a] = (p == 0) ? hi : tf32r(v - __uint_as_float(hi));
            }
            *(uint4*)&frag[q*128 + lane*4] = make_uint4(hv[0], hv[1], hv[2], hv[3]);
        }
        __syncthreads();

        // ---- GEMM: rw0[32e][128ch], 3-pass tf32 ----
        const uint4* Ap = (const uint4*)frag;
        float C[2][2][4];
        #pragma unroll
        for (int mt = 0; mt < 2; mt++)
            #pragma unroll
            for (int nt = 0; nt < 2; nt++)
                #pragma unroll
                for (int i = 0; i < 4; i++) C[mt][nt][i] = 0.0f;

        #pragma unroll
        for (int kt = 0; kt < 8; kt++){
            uint4 ah0 = Ap[(kt*2 + 0)*32 + lane];
            uint4 ah1 = Ap[(kt*2 + 1)*32 + lane];
            uint4 al0 = Ap[((8 + kt)*2 + 0)*32 + lane];
            uint4 al1 = Ap[((8 + kt)*2 + 1)*32 + lane];
            #pragma unroll
            for (int nt = 0; nt < 2; nt++){
                mma8(C[0][nt], ah0, Bh[kt][nt][0], Bh[kt][nt][1]);
                mma8(C[1][nt], ah1, Bh[kt][nt][0], Bh[kt][nt][1]);
                mma8(C[0][nt], al0, Bh[kt][nt][0], Bh[kt][nt][1]);
                mma8(C[1][nt], al1, Bh[kt][nt][0], Bh[kt][nt][1]);
                mma8(C[0][nt], ah0, Bl[kt][nt][0], Bl[kt][nt][1]);
                mma8(C[1][nt], ah1, Bl[kt][nt][0], Bl[kt][nt][1]);
            }
        }

        // ---- scatter straight from C frags: msg = rw0 * scal[snd] ----
        #pragma unroll
        for (int mt = 0; mt < 2; mt++)
            #pragma unroll
            for (int nt = 0; nt < 2; nt++){
                int col = w*16 + nt*8 + ec2;
                int r0 = mt*16 + er, r1 = r0 + 8;
                int s0 = snd_s[r0], d0 = rcv_s[r0];
                float2 ss0 = *(const float2*)&g_scal[s0*FD + col];
                red2(&g_agg[d0*FD + col], C[mt][nt][0]*ss0.x, C[mt][nt][1]*ss0.y);
                int s1 = snd_s[r1], d1 = rcv_s[r1];
                float2 ss1 = *(const float2*)&g_scal[s1*FD + col];
                red2(&g_agg[d1*FD + col], C[mt][nt][2]*ss1.x, C[mt][nt][3]*ss1.y);
            }
    }
}

// ---------------- fused node kernel: lin (l=0) + sc (l=0) + poly ------------
template<bool HAS_SC>
__global__ __launch_bounds__(128) void k_node(
    const float* __restrict__ linW,
    const float* __restrict__ scWp,
    const float* __restrict__ pc)
{
    int tid = threadIdx.x;
    int c16 = blockIdx.x * 16;
    if (c16 >= g_off[NSPEC]) return;
    int s = 0;
    while (c16 >= g_off[s+1]) s++;

    __shared__ int   nodes[16];
    __shared__ float Wl[16*FD];
    __shared__ float Ws[16*FD];
    __shared__ float Aa[16*16];
    __shared__ float As[16*16];
    if (tid < 16) nodes[tid] = g_perm[c16 + tid];

    float aU[16], aV[16];
    #pragma unroll
    for (int r = 0; r < 16; r++){ aU[r] = 0.0f; aV[r] = 0.0f; }

    const float* WL = linW + (size_t)s * 4 * FD * FD;
    const float* WS = HAS_SC ? (scWp + (size_t)s * 4 * FD * FD) : linW;

    for (int ft0 = 0; ft0 < FD; ft0 += 16){
        __syncthreads();
        for (int i = tid; i < 16*FD; i += 128){
            int r = i >> 7, gg = i & 127;
            Wl[i] = WL[(ft0 + r)*FD + gg];
            if (HAS_SC) Ws[i] = WS[(ft0 + r)*FD + gg];
        }
        for (int i = tid; i < 256; i += 128){
            int r = i >> 4, nd = nodes[r];
            int fc = ft0 + (i & 15);
            Aa[i] = (nd < 0) ? 0.0f : g_agg[nd*FD + fc];
            if (HAS_SC) As[i] = (nd < 0) ? 0.0f : g_scal[nd*FD + fc];
        }
        __syncthreads();
        for (int ft = 0; ft < 16; ft++){
            float wl = Wl[ft*FD + tid];
            float ws = HAS_SC ? Ws[ft*FD + tid] : 0.0f;
            #pragma unroll
            for (int r = 0; r < 16; r++){
                aU[r] = fmaf(Aa[r*16 + ft], wl, aU[r]);
                if (HAS_SC) aV[r] = fmaf(As[r*16 + ft], ws, aV[r]);
            }
        }
    }
    const float* C = pc + s*3*FD;
    float c0 = C[tid], c1 = C[FD + tid], c2 = C[2*FD + tid];
    #pragma unroll
    for (int r = 0; r < 16; r++){
        int nd = nodes[r];
        if (nd < 0) continue;
        float sv = 0.5f * aU[r];
        float o  = sv * (c0 + c1*sv + c2*sv*sv);
        if (HAS_SC) o += aV[r];
        g_scal[nd*FD + tid] = o;
        if (!HAS_SC) g_agg[nd*FD + tid] = 0.0f;   // prep for layer 1
    }
}

// ---------------- readouts ---------------------------------------------------
__global__ void k_ro0(const float* __restrict__ ro0, float* __restrict__ out){
    int w = (blockIdx.x*blockDim.x + threadIdx.x) >> 5;
    int lane = threadIdx.x & 31;
    if (w >= NN) return;
    float sacc = 0.0f;
    #pragma unroll
    for (int k = 0; k < 4; k++){
        int f = lane + 32*k;
        sacc = fmaf(g_scal[w*FD + f], ro0[f], sacc);
    }
    #pragma unroll
    for (int o = 16; o; o >>= 1) sacc += __shfl_xor_sync(0xffffffffu, sacc, o);
    if (lane == 0) out[w*2 + 0] = sacc;
}

__global__ void k_ro1(const float* __restrict__ W1, const float* __restrict__ W2,
                      float* __restrict__ out){
    int w = (blockIdx.x*blockDim.x + threadIdx.x) >> 5;
    int lane = threadIdx.x & 31;
    if (w >= NN) return;
    float sc[4];
    #pragma unroll
    for (int k = 0; k < 4; k++) sc[k] = g_scal[w*FD + lane + 32*k];
    float acc = 0.0f;
    #pragma unroll
    for (int j = 0; j < 16; j++){
        float p = 0.0f;
        #pragma unroll
        for (int k = 0; k < 4; k++)
            p = fmaf(sc[k], W1[(lane + 32*k)*16 + j], p);
        #pragma unroll
        for (int o = 16; o; o >>= 1) p += __shfl_xor_sync(0xffffffffu, p, o);
        float h = __fdividef(p, 1.0f + __expf(-p));
        acc = fmaf(h, W2[j], acc);
    }
    if (lane == 0) out[w*2 + 1] = acc;
}

// ---------------- launcher ---------------------------------------------------
extern "C" void kernel_launch(void* const* d_in, const int* in_sizes, int n_in,
                              void* d_out, int out_size)
{
    const float* vectors = (const float*)d_in[0];
    const int*   spec    = (const int*)  d_in[1];
    const int*   snd     = (const int*)  d_in[2];
    const int*   rcv     = (const int*)  d_in[3];
    const float* emb     = (const float*)d_in[4];
    const float* rW1     = (const float*)d_in[5];
    const float* rb1     = (const float*)d_in[6];
    const float* rW2     = (const float*)d_in[7];
    const float* linW    = (const float*)d_in[8];
    const float* pc      = (const float*)d_in[9];
    const float* scW     = (const float*)d_in[10];
    const float* ro0     = (const float*)d_in[11];
    const float* ro1W1   = (const float*)d_in[12];
    const float* ro1W2   = (const float*)d_in[13];
    float* out = (float*)d_out;

    const int LAYER_LIN  = NSPEC * 4 * FD * FD;
    const int LAYER_PC   = NSPEC * 3 * FD;

    float* w2t_ptr;  cudaGetSymbolAddress((void**)&w2t_ptr, g_w2t);

    int nchunks = NN/16 + NSPEC;

    k_cnt0<<<1, 32>>>();                                             // 1
    k_geom<<<(NE + 255)/256, 256>>>(vectors);                        // 2
    k_w2t<<<64, 256>>>(rW2);                                         // 3
    k_init<<<(NN*FD + 255)/256, 256>>>(spec, emb);                   // 4
    k_edge<<<NE/128, 256>>>(rW1, rb1, w2t_ptr, snd, rcv);            // 5  layer 0
    k_b2<<<1, 32>>>();                                               // 6
    k_b4<<<(NN + 255)/256, 256>>>(spec);                             // 7
    k_node<false><<<nchunks, 128>>>(linW, linW, pc);                 // 8 (+agg zero)
    k_ro0<<<(NN*32 + 255)/256, 256>>>(ro0, out);                     // 9
    k_edge<<<NE/128, 256>>>(rW1 + NBASIS*NHID, rb1 + NHID,
                            w2t_ptr + NHID*FD, snd, rcv);            // 10 layer 1
    k_node<true><<<nchunks, 128>>>(linW + LAYER_LIN, scW + LAYER_LIN,
                                   pc + LAYER_PC);                   // 11
    k_ro1<<<(NN*32 + 255)/256, 256>>>(ro1W1, ro1W2, out);            // 12
}

// round 9
// speedup vs baseline: 1.2944x; 1.2944x over previous
#include <cuda_runtime.h>
#include <math.h>

#define NN 10000
#define NE 160000
#define FD 128
#define NBASIS 8
#define NHID 64
#define NSPEC 10
#define NCHK (NE/64)                 // 2500 chunks of 64 edges
#define GRIDE 456                    // 152 SMs x 3 blocks
#define PERM_SZ (NN + 16*NSPEC)
#define RMAXF 5.0f
#define PI_F 3.14159265358979323846f

typedef unsigned long long ull;

// ---------------- device scratch (static, no allocations) ----------------
__device__ __align__(16) float g_rb[NE*NBASIS];     // radial basis per edge [E][8]
__device__ __align__(16) float g_scal[NN*FD];       // node scalar features
__device__ __align__(16) float g_agg[NN*FD];        // aggregated messages
__device__ __align__(16) float g_w2t[2*NHID*FD];    // W2 l=0 cols, transposed [layer][j][ch]
__device__ int   g_cnt[NSPEC];
__device__ int   g_cur[NSPEC];
__device__ int   g_off[NSPEC+1];
__device__ int   g_perm[PERM_SZ];

// ---------------- f32x2 / vector-red helpers --------------------------------
__device__ __forceinline__ ull dup2(float w){
    ull r; asm("mov.b64 %0, {%1, %1};" : "=l"(r) : "f"(w)); return r;
}
__device__ __forceinline__ void ffma2(ull& acc, ull a, ull b){
    asm("fma.rn.f32x2 %0, %1, %2, %0;" : "+l"(acc) : "l"(a), "l"(b));
}
__device__ __forceinline__ float2 unpk(ull v){
    float2 r; asm("mov.b64 {%0, %1}, %2;" : "=f"(r.x), "=f"(r.y) : "l"(v)); return r;
}
__device__ __forceinline__ void red4(float* p, float a, float b, float c, float d){
    asm volatile("red.global.add.v4.f32 [%0], {%1,%2,%3,%4};"
                 :: "l"(p), "f"(a), "f"(b), "f"(c), "f"(d) : "memory");
}

// ---------------- geometry: radial basis (sh[0]==1 is all we need) ----------
__global__ void k_geom(const float* __restrict__ vec){
    int e = blockIdx.x*256 + threadIdx.x;
    if (e >= NE) return;
    float x = vec[3*e+0], y = vec[3*e+1], z = vec[3*e+2];
    float r = sqrtf(x*x + y*y + z*z);
    r = fmaxf(r, 1e-9f);
    float rc  = fminf(r, RMAXF);
    float cut = 0.5f*(__cosf(PI_F*rc/RMAXF) + 1.0f);
    float pref = sqrtf(2.0f/RMAXF) / r * cut;
    float arg = PI_F * r / RMAXF;
    float s1 = __sinf(arg), c2 = 2.0f*__cosf(arg);
    float sm1 = 0.0f, s = s1;
    #pragma unroll
    for (int n = 1; n <= NBASIS; n++){
        g_rb[e*NBASIS + n - 1] = pref * s;
        float sn = c2*s - sm1;
        sm1 = s; s = sn;
    }
}

// ---------------- init (float4): scal = emb[specie]; agg = 0; counts --------
__global__ void k_init(const int* __restrict__ spec, const float* __restrict__ emb){
    int idx = blockIdx.x*256 + threadIdx.x;
    if (idx >= NN*32) return;
    int n = idx >> 5, f4 = idx & 31;
    int s = spec[n];
    ((float4*)g_scal)[idx] = ((const float4*)emb)[s*32 + f4];
    ((float4*)g_agg)[idx]  = make_float4(0.f, 0.f, 0.f, 0.f);
    if (f4 == 0) atomicAdd(&g_cnt[s], 1);
}

// ---------------- W2 transpose + perm init + cnt zero ------------------------
__global__ void k_w2t(const float* __restrict__ W2){
    int idx = blockIdx.x*256 + threadIdx.x;
    if (idx < NSPEC){ g_cnt[idx] = 0; g_cur[idx] = 0; }
    if (idx < 2*NHID*FD){
        int l = idx >> 13, rem = idx & 8191;
        int j = rem >> 7, ch = rem & 127;
        g_w2t[idx] = W2[l*NHID*FD*4 + j*FD*4 + ch*4];
    }
    if (idx < PERM_SZ) g_perm[idx] = -1;
}

__global__ void k_b2(){
    if (threadIdx.x == 0){
        int o = 0;
        for (int s = 0; s < NSPEC; s++){ g_off[s] = o; o += (g_cnt[s] + 15) & ~15; }
        g_off[NSPEC] = o;
    }
}
__global__ void k_b4(const int* __restrict__ spec){
    int n = blockIdx.x*256 + threadIdx.x;
    if (n < NN){
        int s = spec[n];
        int p = atomicAdd(&g_cur[s], 1);
        g_perm[g_off[s] + p] = n;
    }
}

// ---------------- fused edge kernel (persistent-strided, prefetched) ---------
// 456 blocks x 256 threads; block strides chunks of 64 edges. Warp tile:
// 16 edges x 64 ch; lane: 4 edges x 8 ch (f32x2 packed). Row-contig red4.
__global__ __launch_bounds__(256, 3) void k_edge(
    const float* __restrict__ W1, const float* __restrict__ b1,
    const float* __restrict__ W2t,
    const int* __restrict__ snd, const int* __restrict__ rcv)
{
    __shared__ float W2c[NHID*FD];          // 32 KB
    __shared__ float W1s[NBASIS*NHID];
    __shared__ float b1s[NHID];
    __shared__ float rb_s[64*9];
    __shared__ float h_t[NHID*68];          // [j][edge], pitch 68
    __shared__ int   snd_s[64], rcv_s[64];
    int tid = threadIdx.x, lane = tid & 31, w = tid >> 5;

    {   // stage weights once per block
        const float4* src = (const float4*)W2t;
        float4* dst = (float4*)W2c;
        #pragma unroll
        for (int i = 0; i < 8; i++) dst[tid + i*256] = src[tid + i*256];
    }
    for (int i = tid; i < NBASIS*NHID; i += 256) W1s[i] = W1[i];
    if (tid < NHID) b1s[tid] = b1[tid];

    int eq = w & 3, chalf = w >> 2;
    int cg = lane >> 2, eg = lane & 3;
    int ch0 = chalf*64 + cg*4;

    int ck = blockIdx.x;
    float2 pf_rb; int pf_idx = 0;
    {   // prefetch chunk ck
        int e0 = ck*64;
        pf_rb = ((const float2*)g_rb)[e0*4 + tid];
        if (tid < 64) pf_idx = snd[e0 + tid];
        else if (tid < 128) pf_idx = rcv[e0 + tid - 64];
    }

    while (ck < NCHK){
        __syncthreads();                    // prev chunk smem readers done
        {   int i0 = tid*2;
            int o = (i0 >> 3)*9 + (i0 & 7);
            rb_s[o]   = pf_rb.x;
            rb_s[o+1] = pf_rb.y;
            if (tid < 64) snd_s[tid] = pf_idx;
            else if (tid < 128) rcv_s[tid-64] = pf_idx;
        }
        __syncthreads();

        // ---- h = silu(rb @ W1 + b1), h_t[j][e]; warp w owns j in [8w,8w+8) --
        #pragma unroll
        for (int half = 0; half < 2; half++){
            int he = lane + half*32;
            float rbv[NBASIS];
            #pragma unroll
            for (int k = 0; k < NBASIS; k++) rbv[k] = rb_s[he*9 + k];
            #pragma unroll
            for (int q = 0; q < 8; q++){
                int j = w*8 + q;
                float a = b1s[j];
                #pragma unroll
                for (int k = 0; k < NBASIS; k++)
                    a = fmaf(rbv[k], W1s[k*NHID + j], a);
                h_t[j*68 + he] = __fdividef(a, 1.0f + __expf(-a));
            }
        }
        __syncthreads();

        // ---- prefetch next chunk (overlaps GEMM below) ----
        int ckn = ck + GRIDE;
        if (ckn < NCHK){
            int e0n = ckn*64;
            pf_rb = ((const float2*)g_rb)[e0n*4 + tid];
            if (tid < 64) pf_idx = snd[e0n + tid];
            else if (tid < 128) pf_idx = rcv[e0n + tid - 64];
        }

        // ---- rw0 = h @ W2c : 16e x 64ch register tile ----
        ull acc[8][2];
        #pragma unroll
        for (int c = 0; c < 8; c++){ acc[c][0] = 0ULL; acc[c][1] = 0ULL; }

        #pragma unroll 4
        for (int j = 0; j < NHID; j++){
            float4 wa = *(const float4*)&W2c[j*FD + ch0];
            float4 wb = *(const float4*)&W2c[j*FD + ch0 + 32];
            ulonglong2 hh = *(const ulonglong2*)&h_t[j*68 + eq*16 + eg*4];
            ull wd0 = dup2(wa.x), wd1 = dup2(wa.y), wd2 = dup2(wa.z), wd3 = dup2(wa.w);
            ull wd4 = dup2(wb.x), wd5 = dup2(wb.y), wd6 = dup2(wb.z), wd7 = dup2(wb.w);
            ffma2(acc[0][0], hh.x, wd0); ffma2(acc[0][1], hh.y, wd0);
            ffma2(acc[1][0], hh.x, wd1); ffma2(acc[1][1], hh.y, wd1);
            ffma2(acc[2][0], hh.x, wd2); ffma2(acc[2][1], hh.y, wd2);
            ffma2(acc[3][0], hh.x, wd3); ffma2(acc[3][1], hh.y, wd3);
            ffma2(acc[4][0], hh.x, wd4); ffma2(acc[4][1], hh.y, wd4);
            ffma2(acc[5][0], hh.x, wd5); ffma2(acc[5][1], hh.y, wd5);
            ffma2(acc[6][0], hh.x, wd6); ffma2(acc[6][1], hh.y, wd6);
            ffma2(acc[7][0], hh.x, wd7); ffma2(acc[7][1], hh.y, wd7);
        }

        // ---- unpack + scatter ----
        float af[8][4];
        #pragma unroll
        for (int c = 0; c < 8; c++){
            float2 t0 = unpk(acc[c][0]);
            float2 t1 = unpk(acc[c][1]);
            af[c][0] = t0.x; af[c][1] = t0.y; af[c][2] = t1.x; af[c][3] = t1.y;
        }
        #pragma unroll
        for (int i = 0; i < 4; i++){
            int le = eq*16 + eg*4 + i;
            int sidx = snd_s[le], ridx = rcv_s[le];
            float4 ssa = *(const float4*)&g_scal[sidx*FD + ch0];
            float4 ssb = *(const float4*)&g_scal[sidx*FD + ch0 + 32];
            red4(&g_agg[ridx*FD + ch0],
                 af[0][i]*ssa.x, af[1][i]*ssa.y, af[2][i]*ssa.z, af[3][i]*ssa.w);
            red4(&g_agg[ridx*FD + ch0 + 32],
                 af[4][i]*ssb.x, af[5][i]*ssb.y, af[6][i]*ssb.z, af[7][i]*ssb.w);
        }
        ck = ckn;
    }
}

// ---------------- fused node kernel + readout --------------------------------
// lin (l=0) + sc (l=0) + poly, then: L0 -> out[:,0]=scal@ro0W;
// L1 -> out[:,1]=silu(scal@ro1W1)@ro1W2. Layer-1 skips the g_scal store.
template<bool HAS_SC>
__global__ __launch_bounds__(128) void k_node(
    const float* __restrict__ linW,
    const float* __restrict__ scWp,
    const float* __restrict__ pc,
    const float* __restrict__ roA,      // ro0W (L0) / ro1W1 (L1)
    const float* __restrict__ roB,      // unused (L0) / ro1W2 (L1)
    float* __restrict__ out)
{
    int tid = threadIdx.x;
    int c16 = blockIdx.x * 16;
    if (c16 >= g_off[NSPEC]) return;
    int s = 0;
    while (c16 >= g_off[s+1]) s++;

    __shared__ int   nodes[16];
    __shared__ float Wl[16*FD];
    __shared__ float Ws[16*FD];
    __shared__ float Aa[16*16];
    __shared__ float As[16*16];
    if (tid < 16) nodes[tid] = g_perm[c16 + tid];

    float aU[16], aV[16];
    #pragma unroll
    for (int r = 0; r < 16; r++){ aU[r] = 0.0f; aV[r] = 0.0f; }

    const float* WL = linW + (size_t)s * 4 * FD * FD;
    const float* WS = HAS_SC ? (scWp + (size_t)s * 4 * FD * FD) : linW;

    for (int ft0 = 0; ft0 < FD; ft0 += 16){
        __syncthreads();
        for (int i = tid; i < 16*FD; i += 128){
            int r = i >> 7, gg = i & 127;
            Wl[i] = WL[(ft0 + r)*FD + gg];
            if (HAS_SC) Ws[i] = WS[(ft0 + r)*FD + gg];
        }
        for (int i = tid; i < 256; i += 128){
            int r = i >> 4, nd = nodes[r];
            int fc = ft0 + (i & 15);
            Aa[i] = (nd < 0) ? 0.0f : g_agg[nd*FD + fc];
            if (HAS_SC) As[i] = (nd < 0) ? 0.0f : g_scal[nd*FD + fc];
        }
        __syncthreads();
        for (int ft = 0; ft < 16; ft++){
            float wl = Wl[ft*FD + tid];
            float ws = HAS_SC ? Ws[ft*FD + tid] : 0.0f;
            #pragma unroll
            for (int r = 0; r < 16; r++){
                aU[r] = fmaf(Aa[r*16 + ft], wl, aU[r]);
                if (HAS_SC) aV[r] = fmaf(As[r*16 + ft], ws, aV[r]);
            }
        }
    }
    const float* C = pc + s*3*FD;
    float c0 = C[tid], c1 = C[FD + tid], c2 = C[2*FD + tid];
    float ov[16];
    #pragma unroll
    for (int r = 0; r < 16; r++){
        int nd = nodes[r];
        float sv = 0.5f * aU[r];
        float o  = sv * (c0 + c1*sv + c2*sv*sv);
        if (HAS_SC) o += aV[r];
        ov[r] = o;
        if (!HAS_SC && nd >= 0){
            g_scal[nd*FD + tid] = o;
            g_agg[nd*FD + tid]  = 0.0f;     // prep for layer 1
        }
    }

    // ---- fused readout ----
    if (!HAS_SC){
        float w0 = roA[tid];
        __syncthreads();
        #pragma unroll
        for (int r = 0; r < 16; r++) Wl[r*FD + tid] = ov[r]*w0;
        __syncthreads();
        int w = tid >> 5, lane = tid & 31;
        #pragma unroll
        for (int q = 0; q < 4; q++){
            int r = w*4 + q;
            float v = Wl[r*FD+lane] + Wl[r*FD+lane+32]
                    + Wl[r*FD+lane+64] + Wl[r*FD+lane+96];
            #pragma unroll
            for (int o2 = 16; o2; o2 >>= 1) v += __shfl_xor_sync(0xffffffffu, v, o2);
            if (lane == 0 && nodes[r] >= 0) out[nodes[r]*2] = v;
        }
    } else {
        __syncthreads();
        for (int i = tid; i < FD*16; i += 128) Ws[i] = roA[i];   // W1 [f][16]
        #pragma unroll
        for (int r = 0; r < 16; r++) Wl[r*FD + tid] = ov[r];
        __syncthreads();
        int rr = tid >> 3, jj = tid & 7;
        float p0 = 0.0f, p1 = 0.0f;
        #pragma unroll 4
        for (int f = 0; f < FD; f++){
            float sv = Wl[rr*FD + f];
            p0 = fmaf(sv, Ws[f*16 + jj],     p0);
            p1 = fmaf(sv, Ws[f*16 + jj + 8], p1);
        }
        float h0 = __fdividef(p0, 1.0f + __expf(-p0));
        float h1 = __fdividef(p1, 1.0f + __expf(-p1));
        float v = h0*roB[jj] + h1*roB[jj + 8];
        v += __shfl_xor_sync(0xffffffffu, v, 1);
        v += __shfl_xor_sync(0xffffffffu, v, 2);
        v += __shfl_xor_sync(0xffffffffu, v, 4);
        if (jj == 0 && nodes[rr] >= 0) out[nodes[rr]*2 + 1] = v;
    }
}

// ---------------- launcher ---------------------------------------------------
extern "C" void kernel_launch(void* const* d_in, const int* in_sizes, int n_in,
                              void* d_out, int out_size)
{
    const float* vectors = (const float*)d_in[0];
    const int*   spec    = (const int*)  d_in[1];
    const int*   snd     = (const int*)  d_in[2];
    const int*   rcv     = (const int*)  d_in[3];
    const float* emb     = (const float*)d_in[4];
    const float* rW1     = (const float*)d_in[5];
    const float* rb1     = (const float*)d_in[6];
    const float* rW2     = (const float*)d_in[7];
    const float* linW    = (const float*)d_in[8];
    const float* pc      = (const float*)d_in[9];
    const float* scW     = (const float*)d_in[10];
    const float* ro0     = (const float*)d_in[11];
    const float* ro1W1   = (const float*)d_in[12];
    const float* ro1W2   = (const float*)d_in[13];
    float* out = (float*)d_out;

    const int LAYER_LIN  = NSPEC * 4 * FD * FD;
    const int LAYER_PC   = NSPEC * 3 * FD;

    float* w2t_ptr;  cudaGetSymbolAddress((void**)&w2t_ptr, g_w2t);

    int nchunks = NN/16 + NSPEC;

    k_w2t<<<64, 256>>>(rW2);                                         // 1 (+cnt zero)
    k_geom<<<(NE + 255)/256, 256>>>(vectors);                        // 2
    k_init<<<(NN*32 + 255)/256, 256>>>(spec, emb);                   // 3
    k_edge<<<GRIDE, 256>>>(rW1, rb1, w2t_ptr, snd, rcv);             // 4  layer 0
    k_b2<<<1, 32>>>();                                               // 5
    k_b4<<<(NN + 255)/256, 256>>>(spec);                             // 6
    k_node<false><<<nchunks, 128>>>(linW, linW, pc, ro0, ro0, out);  // 7 (+ro0)
    k_edge<<<GRIDE, 256>>>(rW1 + NBASIS*NHID, rb1 + NHID,
                           w2t_ptr + NHID*FD, snd, rcv);             // 8  layer 1
    k_node<true><<<nchunks, 128>>>(linW + LAYER_LIN, scW + LAYER_LIN,
                                   pc + LAYER_PC, ro1W1, ro1W2, out);// 9 (+ro1)
}